// round 1
// baseline (speedup 1.0000x reference)
#include <cuda_runtime.h>
#include <math_constants.h>

// MaxFeatBlockDescriptorLayer:
//   idx[b,k]  = argmax_n prob[b,n,k]          (first index on ties)
//   mask[b,k] = (mean_n prob[b,n,k] > 0.3)
//   out[b,k,:] = mask[b,k] * emb[b, idx[b,k], :]
//
// Shapes: emb [B,16384,2048] f32, prob [B,16384,8] f32, out [B,8,2048] f32.
// One block per (b,k): reduce the prob column, then gather the emb row.

#define N_POS   16384
#define N_CLS   8
#define C_DIM   2048
#define TAU     0.3f
#define NTHREADS 512

__global__ __launch_bounds__(NTHREADS)
void mfbd_kernel(const float* __restrict__ emb,
                 const float* __restrict__ prob,
                 float* __restrict__ out)
{
    const int b = blockIdx.x / N_CLS;
    const int k = blockIdx.x % N_CLS;
    const int tid = threadIdx.x;

    const float* __restrict__ col = prob + (size_t)b * N_POS * N_CLS + k;

    // ---- per-thread strided scan: max + first-index + sum ----
    float best = -CUDART_INF_F;
    int   bidx = 0;
    float sum  = 0.0f;

    #pragma unroll 8
    for (int n = tid; n < N_POS; n += NTHREADS) {
        float v = __ldg(col + (size_t)n * N_CLS);
        sum += v;
        if (v > best) { best = v; bidx = n; }   // strict > keeps first index
    }

    // ---- block reduction ----
    __shared__ float s_val[NTHREADS];
    __shared__ int   s_idx[NTHREADS];
    __shared__ float s_sum[NTHREADS];
    s_val[tid] = best;
    s_idx[tid] = bidx;
    s_sum[tid] = sum;
    __syncthreads();

    #pragma unroll
    for (int s = NTHREADS / 2; s > 0; s >>= 1) {
        if (tid < s) {
            float ov = s_val[tid + s];
            int   oi = s_idx[tid + s];
            float cv = s_val[tid];
            int   ci = s_idx[tid];
            // take other if strictly larger, or equal with smaller index
            if (ov > cv || (ov == cv && oi < ci)) {
                s_val[tid] = ov;
                s_idx[tid] = oi;
            }
            s_sum[tid] += s_sum[tid + s];
        }
        __syncthreads();
    }

    const int   arg  = s_idx[0];
    const float mask = (s_sum[0] * (1.0f / N_POS) > TAU) ? 1.0f : 0.0f;

    // ---- gather emb[b, arg, :] * mask -> out[b, k, :] (float4) ----
    const float4* __restrict__ src =
        (const float4*)(emb + ((size_t)b * N_POS + (size_t)arg) * C_DIM);
    float4* __restrict__ dst =
        (float4*)(out + ((size_t)b * N_CLS + (size_t)k) * C_DIM);

    // C_DIM/4 = 512 float4 == NTHREADS, one per thread
    float4 v = __ldg(src + tid);
    v.x *= mask; v.y *= mask; v.z *= mask; v.w *= mask;
    dst[tid] = v;
}

extern "C" void kernel_launch(void* const* d_in, const int* in_sizes, int n_in,
                              void* d_out, int out_size)
{
    const float* emb  = (const float*)d_in[0];
    const float* prob = (const float*)d_in[1];
    float* out = (float*)d_out;

    const int B = in_sizes[0] / (N_POS * C_DIM);   // = 2

    mfbd_kernel<<<B * N_CLS, NTHREADS>>>(emb, prob, out);
}

// round 2
// speedup vs baseline: 1.0333x; 1.0333x over previous
#include <cuda_runtime.h>

// MaxFeatBlockDescriptorLayer, two-phase:
//   K1: chunked coalesced reduction of prob [B,16384,8] -> per-chunk
//       (packed max|~idx, sum) partials per (b,k). No atomics; fixed slots.
//   K2: reduce 64 partials per (b,k), then gather emb[b,argmax,:] * mask.
//
// argmax tie-break = first index, matched by packing (bits(v)<<32)|(N-1-n)
// and taking max (prob >= 0 so float bits are order-monotonic).

#define N_POS    16384
#define N_CLS    8
#define C_DIM    2048
#define TAU      0.3f
#define CHUNKS   64                      // chunks per batch
#define POS_PC   (N_POS / CHUNKS)        // 256 positions per chunk
#define K1_THREADS 256
#define K2_THREADS 512
#define MAX_B    8

__device__ unsigned long long g_pack[MAX_B * N_CLS * CHUNKS];
__device__ float              g_sum [MAX_B * N_CLS * CHUNKS];

__global__ __launch_bounds__(K1_THREADS)
void mfbd_reduce(const float* __restrict__ prob)
{
    const int b     = blockIdx.x / CHUNKS;
    const int chunk = blockIdx.x % CHUNKS;
    const int t     = threadIdx.x;

    __shared__ float sv[POS_PC * N_CLS];   // 256 pos x 8 classes = 8KB

    // contiguous chunk: POS_PC*8 floats = 512 float4; 256 threads x 2
    const float4* __restrict__ p4 =
        (const float4*)prob + ((size_t)b * N_POS + (size_t)chunk * POS_PC) * 2;

    float4 a0 = __ldg(p4 + t);
    float4 a1 = __ldg(p4 + t + K1_THREADS);
    ((float4*)sv)[t]              = a0;
    ((float4*)sv)[t + K1_THREADS] = a1;
    __syncthreads();

    const int w    = t >> 5;    // warp = class (8 warps)
    const int lane = t & 31;

    unsigned long long best = 0ULL;
    float s = 0.0f;

    #pragma unroll
    for (int i = 0; i < POS_PC / 32; ++i) {       // 8 positions per lane
        const int p = lane + i * 32;
        const float v = sv[p * N_CLS + w];
        s += v;
        const unsigned comp = (unsigned)(N_POS - 1 - (chunk * POS_PC + p));
        const unsigned long long pk =
            ((unsigned long long)__float_as_uint(v) << 32) | comp;
        best = best > pk ? best : pk;
    }

    #pragma unroll
    for (int off = 16; off > 0; off >>= 1) {
        const unsigned long long ob = __shfl_down_sync(0xffffffffu, best, off);
        best = best > ob ? best : ob;
        s += __shfl_down_sync(0xffffffffu, s, off);
    }

    if (lane == 0) {
        const int slot = (b * N_CLS + w) * CHUNKS + chunk;
        g_pack[slot] = best;
        g_sum[slot]  = s;
    }
}

__global__ __launch_bounds__(K2_THREADS)
void mfbd_gather(const float* __restrict__ emb, float* __restrict__ out)
{
    const int b = blockIdx.x / N_CLS;
    const int k = blockIdx.x % N_CLS;
    const int t = threadIdx.x;

    __shared__ unsigned long long sp[CHUNKS];
    __shared__ float ss[CHUNKS];
    __shared__ int   s_arg;
    __shared__ float s_mask;

    const int base = (b * N_CLS + k) * CHUNKS;
    if (t < CHUNKS) {
        sp[t] = g_pack[base + t];
        ss[t] = g_sum[base + t];
    }
    __syncthreads();

    if (t < 32) {
        unsigned long long bp = sp[t] > sp[t + 32] ? sp[t] : sp[t + 32];
        float s = ss[t] + ss[t + 32];
        #pragma unroll
        for (int off = 16; off > 0; off >>= 1) {
            const unsigned long long ob = __shfl_down_sync(0xffffffffu, bp, off);
            bp = bp > ob ? bp : ob;
            s += __shfl_down_sync(0xffffffffu, s, off);
        }
        if (t == 0) {
            s_arg  = N_POS - 1 - (int)(unsigned)(bp & 0xffffffffu);
            s_mask = (s * (1.0f / N_POS) > TAU) ? 1.0f : 0.0f;
        }
    }
    __syncthreads();

    const float4* __restrict__ src =
        (const float4*)(emb + ((size_t)b * N_POS + (size_t)s_arg) * C_DIM);
    float4* __restrict__ dst =
        (float4*)(out + ((size_t)b * N_CLS + (size_t)k) * C_DIM);

    float4 v = __ldg(src + t);                    // 512 float4 = 2048 floats
    const float m = s_mask;
    v.x *= m; v.y *= m; v.z *= m; v.w *= m;
    dst[t] = v;
}

extern "C" void kernel_launch(void* const* d_in, const int* in_sizes, int n_in,
                              void* d_out, int out_size)
{
    const float* emb  = (const float*)d_in[0];
    const float* prob = (const float*)d_in[1];
    float* out = (float*)d_out;

    const int B = in_sizes[0] / (N_POS * C_DIM);   // = 2

    mfbd_reduce<<<B * CHUNKS, K1_THREADS>>>(prob);
    mfbd_gather<<<B * N_CLS, K2_THREADS>>>(emb, out);
}